// round 12
// baseline (speedup 1.0000x reference)
#include <cuda_runtime.h>
#include <cuda_bf16.h>

// SEIR Euler — fused producer/consumer, work-queue, ILP-4 store streams.
//
// History: two-kernel 96.1us -> fused 92.8 -> +workqueue/ILP-2 88.1us
// (5.52 TB/s, DRAM 67.5%, issue 28% -> still store-supply limited).
// This round: each warp pulls FOUR chunks per queue grab and interleaves
// 4 independent chain+store streams (4 STG.128 per chain step).
// Producer flags are monotonic -> spin only on the highest chunk needed.
// All synchronization intra-CTA -> deadlock-free at any residency.

#define CHUNK      32
#define MAX_CHUNKS 32          // fused path supports t <= 1024
#define BPC        32          // regions per CTA (= producer warp lanes)
#define BLOCK      256
#define GRAB       4

__device__ __forceinline__ float4 seir_step(float4 v, float bh, float gh, float sh)
{
    const float S = v.x, E = v.y, I = v.z, R = v.w;
    const float p = bh * S;
    float4 r;
    r.x = __fmaf_rn(-p, I, S);
    r.y = __fmaf_rn( p, I, __fmaf_rn(-sh, E, E));
    r.z = __fmaf_rn( sh, E, __fmaf_rn(-gh, I, I));
    r.w = __fmaf_rn( gh, I, R);
    return r;
}

__global__ void __launch_bounds__(BLOCK) seir_fused_kernel(
    const float* __restrict__ initial,
    const float* __restrict__ beta,
    const float* __restrict__ gamma,
    const float* __restrict__ sigma,
    float4* __restrict__ out,
    int B, int t)
{
    __shared__ float4   ckpt[MAX_CHUNKS][BPC];
    __shared__ unsigned flags[MAX_CHUNKS];
    __shared__ unsigned work_ctr;

    const int g    = blockIdx.x;
    const int tid  = threadIdx.x;
    const int wid  = tid >> 5;
    const int lane = tid & 31;
    const int nchunks = t / CHUNK;            // exact in fused path
    const int base_b  = g * BPC;

    const float step = 0.5f;
    const float bh = beta[0]  * step;
    const float gh = gamma[0] * step;
    const float sh = sigma[0] * step;

    for (int i = tid; i < MAX_CHUNKS; i += BLOCK) flags[i] = 0u;
    if (tid == 0) work_ctr = 0u;
    __syncthreads();

    volatile unsigned* vflags = flags;

    if (wid == 0) {
        // ---- Producer: serial chain for 32 regions, publish checkpoints ----
        const int b = base_b + lane;
        float4 v = make_float4(initial[0 * B + b], initial[1 * B + b],
                               initial[2 * B + b], initial[3 * B + b]);
        for (int c = 0; c < nchunks; ++c) {
            ckpt[c][lane] = v;
            __stcs(&out[(size_t)c * CHUNK * B + b], v);  // checkpoint out slot
            __syncwarp();
            if (lane == 0) { __threadfence_block(); vflags[c] = 1u; }
            if (c + 1 < nchunks) {
                #pragma unroll 8
                for (int j = 0; j < CHUNK; ++j)
                    v = seir_step(v, bh, gh, sh);
            }
        }
        // fall through: producer joins the consumer pool
    }

    // ---- Consumers (all warps): pull GRAB chunks per queue grab ----
    for (;;) {
        unsigned base;
        if (lane == 0) base = atomicAdd(&work_ctr, (unsigned)GRAB);
        base = __shfl_sync(0xFFFFFFFFu, base, 0);
        if (base >= (unsigned)nchunks) break;

        const int c0 = (int)base;
        const int cmax = min(c0 + GRAB - 1, nchunks - 1);

        // Flags are set in increasing order -> waiting on cmax covers all.
        while (vflags[cmax] == 0u) { }
        __threadfence_block();

        if (c0 + GRAB <= nchunks) {
            // Full ILP-4 path: 4 independent chain+store streams.
            float4 v0 = ckpt[c0 + 0][lane];
            float4 v1 = ckpt[c0 + 1][lane];
            float4 v2 = ckpt[c0 + 2][lane];
            float4 v3 = ckpt[c0 + 3][lane];
            size_t i0 = (size_t)(c0 + 0) * CHUNK * B + base_b + lane;
            size_t i1 = (size_t)(c0 + 1) * CHUNK * B + base_b + lane;
            size_t i2 = (size_t)(c0 + 2) * CHUNK * B + base_b + lane;
            size_t i3 = (size_t)(c0 + 3) * CHUNK * B + base_b + lane;
            #pragma unroll
            for (int j = 1; j < CHUNK; ++j) {
                v0 = seir_step(v0, bh, gh, sh);
                v1 = seir_step(v1, bh, gh, sh);
                v2 = seir_step(v2, bh, gh, sh);
                v3 = seir_step(v3, bh, gh, sh);
                i0 += B; i1 += B; i2 += B; i3 += B;
                __stcs(&out[i0], v0);
                __stcs(&out[i1], v1);
                __stcs(&out[i2], v2);
                __stcs(&out[i3], v3);
            }
        } else {
            // Tail: remaining 1-3 chunks, scalar per chunk.
            for (int c = c0; c <= cmax; ++c) {
                float4 v = ckpt[c][lane];
                size_t idx = (size_t)c * CHUNK * B + base_b + lane;
                #pragma unroll
                for (int j = 1; j < CHUNK; ++j) {
                    v = seir_step(v, bh, gh, sh);
                    idx += B;
                    __stcs(&out[idx], v);
                }
            }
        }
    }
}

// ---- Fallback two-kernel path (known-good) for generic shapes ----
__global__ void __launch_bounds__(128) seir_ckpt_kernel(
    const float* __restrict__ initial, const float* __restrict__ beta,
    const float* __restrict__ gamma,   const float* __restrict__ sigma,
    float4* __restrict__ out, int B, int t)
{
    const int b = blockIdx.x * blockDim.x + threadIdx.x;
    if (b >= B) return;
    const float step = 0.5f;
    const float bh = beta[0]*step, gh = gamma[0]*step, sh = sigma[0]*step;
    float4 v = make_float4(initial[0*B+b], initial[1*B+b],
                           initial[2*B+b], initial[3*B+b]);
    out[b] = v;
    const int nchunks = (t + CHUNK - 1) / CHUNK;
    for (int c = 1; c < nchunks; ++c) {
        const int base = (c - 1) * CHUNK;
        const int steps = min(CHUNK, t - base);
        for (int j = 0; j < steps; ++j) v = seir_step(v, bh, gh, sh);
        if (c * CHUNK < t) out[(size_t)c * CHUNK * B + b] = v;
    }
}

__global__ void __launch_bounds__(256) seir_store_kernel(
    const float* __restrict__ beta, const float* __restrict__ gamma,
    const float* __restrict__ sigma, float4* __restrict__ out,
    int B, int t)
{
    const int tid = blockIdx.x * blockDim.x + threadIdx.x;
    const int c  = tid / B;
    const int bb = tid - c * B;
    const int n0 = c * CHUNK;
    if (n0 >= t || bb >= B) return;
    const float step = 0.5f;
    const float bh = beta[0]*step, gh = gamma[0]*step, sh = sigma[0]*step;
    size_t idx = (size_t)n0 * B + bb;
    float4 v = out[idx];
    const int nlast = min(n0 + CHUNK, t);
    for (int n = n0 + 1; n < nlast; ++n) {
        v = seir_step(v, bh, gh, sh);
        idx += B;
        __stcs(&out[idx], v);
    }
}

extern "C" void kernel_launch(void* const* d_in, const int* in_sizes, int n_in,
                              void* d_out, int out_size)
{
    const float* initial = (const float*)d_in[0];   // 4*B elements
    const float* beta    = (const float*)d_in[1];
    const float* gamma   = (const float*)d_in[2];
    const float* sigma   = (const float*)d_in[3];

    const int B = in_sizes[0] / 4;
    const int t = (B > 0) ? (out_size / (4 * B)) : 0;
    if (B <= 0 || t <= 0) return;

    if ((B % BPC) == 0 && (t % CHUNK) == 0 && (t / CHUNK) <= MAX_CHUNKS) {
        seir_fused_kernel<<<B / BPC, BLOCK>>>(initial, beta, gamma, sigma,
                                              (float4*)d_out, B, t);
    } else {
        const int nchunks = (t + CHUNK - 1) / CHUNK;
        const long long total = (long long)nchunks * B;
        seir_ckpt_kernel<<<(B + 127) / 128, 128>>>(initial, beta, gamma, sigma,
                                                   (float4*)d_out, B, t);
        seir_store_kernel<<<(int)((total + 255) / 256), 256>>>(
            beta, gamma, sigma, (float4*)d_out, B, t);
    }
}